// round 9
// baseline (speedup 1.0000x reference)
#include <cuda_runtime.h>
#include <cstdint>
#include <math.h>

#define BB 16
#define FF 2048
#define SS 512
#define DD 256
#define NNODE (BB * SS)           // 8192
#define NEDGE (BB * FF)           // 32768

// gather tiling
#define GCH 16                    // column chunks (32 cols each)
#define GNG 28                    // node groups
#define GNPB 293                  // nodes per block (28*293 >= 8192)
#define GSMEM ((2 * 512 * 32 + 2 * 8 * 32) * 4)   // 133120 bytes

// ------------- device scratch (static globals; no allocation) -------------
__device__ float g_T1[512 * 512];   // pos_emb @ W1[0:256,:]
__device__ float g_T3[512 * 512];   // pos_emb @ W1[512:768,:]
__device__ float g_TP[8 * 512];     // pred_emb @ W1[256:512,:] + b1
__device__ float g_TR[8 * 512];     // role_emb @ W1[512:768,:]
__device__ float g_agg[NNODE * 512];// per-node sum of gelu(h)
__device__ int   g_cnt[NNODE];      // zeroed by k_gemm epilogue each run
__device__ int   g_off[NNODE + 1];
__device__ int   g_fill[NNODE];
__device__ unsigned g_msgs[2 * NEDGE];
__device__ float g_pooled[BB * DD]; // zeroed by k_latent each run

// ------------- helpers -------------
__device__ __forceinline__ unsigned long long ffma2(unsigned long long a,
                                                    unsigned long long b,
                                                    unsigned long long c) {
    unsigned long long d;
    asm("fma.rn.f32x2 %0, %1, %2, %3;" : "=l"(d) : "l"(a), "l"(b), "l"(c));
    return d;
}
__device__ __forceinline__ unsigned long long dup2(float a) {
    unsigned long long d;
    asm("mov.b64 %0, {%1, %1};" : "=l"(d) : "f"(a));
    return d;
}
__device__ __forceinline__ float2 unpk(unsigned long long u) {
    float2 r;
    asm("mov.b64 {%0, %1}, %2;" : "=f"(r.x), "=f"(r.y) : "l"(u));
    return r;
}

// ------------- k1: precompute tables -------------
// C[rows,512] = A[rows,256] @ W1[wOff:wOff+256, :]   (+ b1 for TP)
__global__ void __launch_bounds__(256) k_tables(const float* __restrict__ pos,
                                                const float* __restrict__ pre,
                                                const float* __restrict__ rol,
                                                const float* __restrict__ W1,
                                                const float* __restrict__ b1) {
    int seg = blockIdx.z;
    const float* A; float* C; int rowsTot; int wOff;
    if (seg == 0)      { A = pos; C = g_T1; rowsTot = 512; wOff = 0; }
    else if (seg == 1) { A = pos; C = g_T3; rowsTot = 512; wOff = 512; }
    else if (seg == 2) { A = pre; C = g_TP; rowsTot = 8;   wOff = 256; }
    else               { A = rol; C = g_TR; rowsTot = 8;   wOff = 512; }
    int r0 = blockIdx.y * 32;
    if (r0 >= rowsTot) return;

    __shared__ float A_sm[32][256];
    int t = threadIdx.x;
    #pragma unroll
    for (int i = 0; i < 8; i++) {
        int fi = t + 256 * i;
        int row = fi >> 6, q = fi & 63;
        float4 v = make_float4(0.f, 0.f, 0.f, 0.f);
        if (r0 + row < rowsTot)
            v = *(const float4*)&A[(size_t)(r0 + row) * 256 + q * 4];
        A_sm[row][q * 4 + 0] = v.x; A_sm[row][q * 4 + 1] = v.y;
        A_sm[row][q * 4 + 2] = v.z; A_sm[row][q * 4 + 3] = v.w;
    }
    __syncthreads();

    int col = blockIdx.x * 64 + (t & 63);
    int rg  = t >> 6;
    float acc[8] = {0, 0, 0, 0, 0, 0, 0, 0};
    #pragma unroll 4
    for (int k4 = 0; k4 < 64; k4++) {
        float w0 = W1[(size_t)(wOff + k4 * 4 + 0) * 512 + col];
        float w1 = W1[(size_t)(wOff + k4 * 4 + 1) * 512 + col];
        float w2 = W1[(size_t)(wOff + k4 * 4 + 2) * 512 + col];
        float w3 = W1[(size_t)(wOff + k4 * 4 + 3) * 512 + col];
        #pragma unroll
        for (int j = 0; j < 8; j++) {
            float4 a = *(const float4*)&A_sm[rg * 8 + j][k4 * 4];
            acc[j] = fmaf(a.x, w0, acc[j]);
            acc[j] = fmaf(a.y, w1, acc[j]);
            acc[j] = fmaf(a.z, w2, acc[j]);
            acc[j] = fmaf(a.w, w3, acc[j]);
        }
    }
    float bias = (seg == 2) ? b1[col] : 0.0f;
    #pragma unroll
    for (int j = 0; j < 8; j++) {
        int r = r0 + rg * 8 + j;
        if (r < rowsTot) C[(size_t)r * 512 + col] = acc[j] + bias;
    }
}

// ------------- k2a: count messages per destination node -------------
__global__ void k_count(const int* __restrict__ a0, const int* __restrict__ a1,
                        const int* __restrict__ pr) {
    int e = blockIdx.x * 256 + threadIdx.x;
    if (e >= NEDGE) return;
    int b = e >> 11;
    int A0 = a0[e], A1 = a1[e], P = pr[e];
    int dst = (P == 1) ? A0 : A1;
    atomicAdd(&g_cnt[b * SS + dst], 1);
    if (P >= 2) atomicAdd(&g_cnt[b * SS + A0], 1);
}

// ------------- k2b: exclusive scan via warp shuffles (one block) -------------
__global__ void __launch_bounds__(1024) k_scan() {
    __shared__ int wsum[32];
    int t = threadIdx.x, lane = t & 31, warp = t >> 5;
    int base = t * 8;
    int loc[8], s = 0;
    #pragma unroll
    for (int i = 0; i < 8; i++) { loc[i] = g_cnt[base + i]; s += loc[i]; }
    // inclusive warp scan of per-thread sums
    int inc = s;
    #pragma unroll
    for (int o = 1; o < 32; o <<= 1) {
        int v = __shfl_up_sync(0xffffffffu, inc, o);
        if (lane >= o) inc += v;
    }
    if (lane == 31) wsum[warp] = inc;
    __syncthreads();
    if (warp == 0) {
        int ws = wsum[lane];
        int winc = ws;
        #pragma unroll
        for (int o = 1; o < 32; o <<= 1) {
            int v = __shfl_up_sync(0xffffffffu, winc, o);
            if (lane >= o) winc += v;
        }
        wsum[lane] = winc - ws;   // exclusive warp base
    }
    __syncthreads();
    int excl = wsum[warp] + inc - s;
    #pragma unroll
    for (int i = 0; i < 8; i++) {
        g_off[base + i] = excl;
        g_fill[base + i] = excl;
        excl += loc[i];
    }
    if (t == 1023) g_off[NNODE] = excl;
}

// ------------- k2c: fill message descriptors -------------
// word: bits[0:9) T1 row, [9:18) third row, [18:21) pred, bit21 third-is-role
__global__ void k_fill(const int* __restrict__ a0, const int* __restrict__ a1,
                       const int* __restrict__ pr, const int* __restrict__ ro) {
    int e = blockIdx.x * 256 + threadIdx.x;
    if (e >= NEDGE) return;
    int b = e >> 11;
    int A0 = a0[e], A1 = a1[e], P = pr[e];
    int isr = (P == 1);
    int dstF = isr ? A0 : A1;
    int third = isr ? (ro[e] + 1) : A1;
    unsigned wf = (unsigned)A0 | ((unsigned)third << 9) | ((unsigned)P << 18) |
                  ((unsigned)isr << 21);
    int pos = atomicAdd(&g_fill[b * SS + dstF], 1);
    g_msgs[pos] = wf;
    if (P >= 2) {
        unsigned wb = (unsigned)A1 | ((unsigned)A0 << 9) | ((unsigned)P << 18);
        int pos2 = atomicAdd(&g_fill[b * SS + A0], 1);
        g_msgs[pos2] = wb;
    }
}

// ------------- k3: gather + gelu accumulate, smem-tiled tables -------------
// grid (GNG, GCH); block 512. Each block stages a 32-col slice of all 4 tables
// in shared memory (conflict-free, stride 32), then each warp owns nodes and
// accumulates gelu(T1[r1]+TP[p]+T3/TR[r3]) per column-lane from smem.
__global__ void __launch_bounds__(512) k_gather() {
    extern __shared__ float sm[];
    float* sT1 = sm;                       // 512*32
    float* sT3 = sm + 512 * 32;            // 512*32
    float* sTP = sm + 2 * 512 * 32;        // 8*32
    float* sTR = sTP + 8 * 32;             // 8*32

    int t = threadIdx.x;
    int c0 = blockIdx.y * 32;

    // stage big tables: 4096 float4 pairs
    for (int i = t; i < 4096; i += 512) {
        int r = i >> 3, q = i & 7;
        *(float4*)&sT1[r * 32 + q * 4] =
            *(const float4*)&g_T1[(size_t)r * 512 + c0 + q * 4];
        *(float4*)&sT3[r * 32 + q * 4] =
            *(const float4*)&g_T3[(size_t)r * 512 + c0 + q * 4];
    }
    if (t < 128) {
        int tab = t >> 6, r = (t >> 3) & 7, q = t & 7;
        const float* src = tab ? g_TR : g_TP;
        float* dst = tab ? sTR : sTP;
        *(float4*)&dst[r * 32 + q * 4] =
            *(const float4*)&src[(size_t)r * 512 + c0 + q * 4];
    }
    __syncthreads();

    int lane = t & 31, warp = t >> 5;
    int nbase = blockIdx.x * GNPB;

    for (int nn = warp; nn < GNPB; nn += 16) {
        int n = nbase + nn;
        if (n >= NNODE) break;
        int beg = g_off[n], end = g_off[n + 1];
        float acc = 0.f;
        for (int mb = beg; mb < end; mb += 32) {
            int cnt = end - mb;
            if (cnt > 32) cnt = 32;
            unsigned wv = 0;
            if (lane < cnt) wv = g_msgs[mb + lane];
            #pragma unroll 4
            for (int j = 0; j < cnt; j++) {
                unsigned w = __shfl_sync(0xffffffffu, wv, j);
                int r1 = w & 511;
                int r3 = (w >> 9) & 511;
                int p  = (w >> 18) & 7;
                const float* b3 = (w & (1u << 21)) ? sTR : sT3;
                float a = sT1[r1 * 32 + lane];
                float b = sTP[p * 32 + lane];
                float c = b3[r3 * 32 + lane];
                float x = a + b + c;
                // gelu(x) = 0.5x + 0.3989422804*x^2*(1 - x^2/6 + x^4/40)
                // (|x| < 0.07 in practice; truncation error ~2e-9)
                float x2 = x * x;
                float q = fmaf(x2, 0.025f, -0.16666667f);
                q = fmaf(x2, q, 1.0f);
                acc = fmaf(0.5f, x, acc);
                acc = fmaf(0.3989422804f * x2, q, acc);
            }
        }
        g_agg[(size_t)n * 512 + c0 + lane] = acc;
    }
}

// ------------- k4: node GEMM (8192x512 @ 512x256) + fused LN + pooled mean ----
__global__ void __launch_bounds__(256) k_gemm(const float* __restrict__ W2,
                                              const float* __restrict__ pos,
                                              const float* __restrict__ b2,
                                              const float* __restrict__ lng,
                                              const float* __restrict__ lnb) {
    __shared__ __align__(16) float Gs[64][36];
    __shared__ __align__(16) float Ws[32][260];
    int t = threadIdx.x;
    int lane = t & 31, warp = t >> 5;
    int row0 = blockIdx.x * 64;

    unsigned long long acc[8][4];
    #pragma unroll
    for (int j = 0; j < 8; j++)
        #pragma unroll
        for (int c = 0; c < 4; c++) acc[j][c] = 0ULL;

    for (int kc = 0; kc < 512; kc += 32) {
        #pragma unroll
        for (int i = 0; i < 2; i++) {
            int q = t * 2 + i;
            int r = q >> 3, c4 = q & 7;
            float4 v = *(const float4*)&g_agg[(size_t)(row0 + r) * 512 + kc + c4 * 4];
            Gs[r][c4 * 4 + 0] = v.x; Gs[r][c4 * 4 + 1] = v.y;
            Gs[r][c4 * 4 + 2] = v.z; Gs[r][c4 * 4 + 3] = v.w;
        }
        #pragma unroll
        for (int i = 0; i < 8; i++) {
            int q = t + i * 256;
            int r = q >> 6, c4 = q & 63;
            float4 v = *(const float4*)&W2[(size_t)(kc + r) * 256 + c4 * 4];
            Ws[r][c4 * 4 + 0] = v.x; Ws[r][c4 * 4 + 1] = v.y;
            Ws[r][c4 * 4 + 2] = v.z; Ws[r][c4 * 4 + 3] = v.w;
        }
        __syncthreads();
        #pragma unroll 4
        for (int kk = 0; kk < 32; kk++) {
            unsigned long long bp[4];
            #pragma unroll
            for (int c = 0; c < 4; c++)
                bp[c] = *(const unsigned long long*)&Ws[kk][2 * lane + 64 * c];
            #pragma unroll
            for (int j = 0; j < 8; j++) {
                unsigned long long av = dup2(Gs[8 * warp + j][kk]);
                #pragma unroll
                for (int c = 0; c < 4; c++) acc[j][c] = ffma2(av, bp[c], acc[j][c]);
            }
        }
        __syncthreads();
    }

    // epilogue: x = C + pos_emb[s] + cnt*b2 ; LayerNorm ; pooled sum
    float2 glv[4], blv[4], b2v[4];
    #pragma unroll
    for (int c = 0; c < 4; c++) {
        glv[c] = *(const float2*)&lng[2 * lane + 64 * c];
        blv[c] = *(const float2*)&lnb[2 * lane + 64 * c];
        b2v[c] = *(const float2*)&b2[2 * lane + 64 * c];
    }
    float2 pool[4];
    #pragma unroll
    for (int c = 0; c < 4; c++) pool[c] = make_float2(0.f, 0.f);

    int rbase = row0 + 8 * warp;
    #pragma unroll
    for (int j = 0; j < 8; j++) {
        int rg = rbase + j;
        int s = rg & 511;
        float cr = (float)g_cnt[rg];
        if (lane == 0) g_cnt[rg] = 0;      // re-zero for next run
        float2 xv[4];
        float s1 = 0.f, s2 = 0.f;
        #pragma unroll
        for (int c = 0; c < 4; c++) {
            float2 pe = *(const float2*)&pos[(size_t)s * 256 + 2 * lane + 64 * c];
            float2 a = unpk(acc[j][c]);
            float x0 = a.x + pe.x + cr * b2v[c].x;
            float x1 = a.y + pe.y + cr * b2v[c].y;
            xv[c] = make_float2(x0, x1);
            s1 += x0 + x1;
            s2 = fmaf(x0, x0, s2);
            s2 = fmaf(x1, x1, s2);
        }
        #pragma unroll
        for (int off = 16; off > 0; off >>= 1) {
            s1 += __shfl_xor_sync(0xffffffff, s1, off);
            s2 += __shfl_xor_sync(0xffffffff, s2, off);
        }
        float mu = s1 * (1.0f / 256.0f);
        float var = fmaf(-mu, mu, s2 * (1.0f / 256.0f));
        float iv = rsqrtf(var + 1e-5f);
        #pragma unroll
        for (int c = 0; c < 4; c++) {
            float n0 = fmaf((xv[c].x - mu) * iv, glv[c].x, blv[c].x);
            float n1 = fmaf((xv[c].y - mu) * iv, glv[c].y, blv[c].y);
            pool[c].x += n0;
            pool[c].y += n1;
        }
    }
    int bb = rbase >> 9;
    float* pp = g_pooled + bb * 256;
    #pragma unroll
    for (int c = 0; c < 4; c++) {
        atomicAdd(&pp[2 * lane + 64 * c + 0], pool[c].x * (1.0f / 512.0f));
        atomicAdd(&pp[2 * lane + 64 * c + 1], pool[c].y * (1.0f / 512.0f));
    }
}

// ------------- k5: latent MLP (16x256 -> 16x512) -------------
__global__ void __launch_bounds__(512) k_latent(const float* __restrict__ Wl1,
                                                const float* __restrict__ bl1,
                                                const float* __restrict__ Wl2,
                                                const float* __restrict__ bl2,
                                                float* __restrict__ out) {
    __shared__ float ps[256];
    __shared__ float mid[512];
    int b = blockIdx.x, t = threadIdx.x;
    if (t < 256) {
        ps[t] = g_pooled[b * 256 + t];
        g_pooled[b * 256 + t] = 0.0f;      // re-zero for next run
    }
    __syncthreads();
    float a0 = 0.f, a1 = 0.f, a2 = 0.f, a3 = 0.f;
    #pragma unroll 4
    for (int k = 0; k < 256; k += 4) {
        a0 = fmaf(ps[k + 0], Wl1[(size_t)(k + 0) * 512 + t], a0);
        a1 = fmaf(ps[k + 1], Wl1[(size_t)(k + 1) * 512 + t], a1);
        a2 = fmaf(ps[k + 2], Wl1[(size_t)(k + 2) * 512 + t], a2);
        a3 = fmaf(ps[k + 3], Wl1[(size_t)(k + 3) * 512 + t], a3);
    }
    float h = a0 + a1 + a2 + a3 + bl1[t];
    mid[t] = 0.5f * h * (1.0f + erff(h * 0.7071067811865476f));
    __syncthreads();
    a0 = a1 = a2 = a3 = 0.f;
    #pragma unroll 4
    for (int j = 0; j < 512; j += 4) {
        a0 = fmaf(mid[j + 0], Wl2[(size_t)(j + 0) * 512 + t], a0);
        a1 = fmaf(mid[j + 1], Wl2[(size_t)(j + 1) * 512 + t], a1);
        a2 = fmaf(mid[j + 2], Wl2[(size_t)(j + 2) * 512 + t], a2);
        a3 = fmaf(mid[j + 3], Wl2[(size_t)(j + 3) * 512 + t], a3);
    }
    out[b * 512 + t] = a0 + a1 + a2 + a3 + bl2[t];
}

// ------------- launch -------------
extern "C" void kernel_launch(void* const* d_in, const int* in_sizes, int n_in,
                              void* d_out, int out_size) {
    const int* a0 = (const int*)d_in[0];
    const int* a1 = (const int*)d_in[1];
    const int* pr = (const int*)d_in[2];
    const int* ro = (const int*)d_in[3];
    int base = (n_in > 4 && in_sizes[4] == 1) ? 5 : 4;
    const float* pos = (const float*)d_in[base + 0];
    const float* pre = (const float*)d_in[base + 1];
    const float* rol = (const float*)d_in[base + 2];
    const float* W1  = (const float*)d_in[base + 3];
    const float* b1  = (const float*)d_in[base + 4];
    const float* W2  = (const float*)d_in[base + 5];
    const float* b2  = (const float*)d_in[base + 6];
    const float* lng = (const float*)d_in[base + 7];
    const float* lnb = (const float*)d_in[base + 8];
    const float* Wl1 = (const float*)d_in[base + 9];
    const float* bl1 = (const float*)d_in[base + 10];
    const float* Wl2 = (const float*)d_in[base + 11];
    const float* bl2 = (const float*)d_in[base + 12];
    float* out = (float*)d_out;

    cudaFuncSetAttribute(k_gather, cudaFuncAttributeMaxDynamicSharedMemorySize,
                         GSMEM);

    k_tables<<<dim3(8, 16, 4), 256>>>(pos, pre, rol, W1, b1);
    k_count<<<NEDGE / 256, 256>>>(a0, a1, pr);
    k_scan<<<1, 1024>>>();
    k_fill<<<NEDGE / 256, 256>>>(a0, a1, pr, ro);
    k_gather<<<dim3(GNG, GCH), 512, GSMEM>>>();
    k_gemm<<<NNODE / 64, 256>>>(W2, pos, b2, lng, lnb);
    k_latent<<<BB, 512>>>(Wl1, bl1, Wl2, bl2, out);
}

// round 16
// speedup vs baseline: 1.1706x; 1.1706x over previous
#include <cuda_runtime.h>
#include <cstdint>
#include <math.h>

#define BB 16
#define FF 2048
#define SS 512
#define DD 256
#define NNODE (BB * SS)           // 8192
#define NEDGE (BB * FF)           // 32768

typedef unsigned long long u64;

// ------------- device scratch (static globals; no allocation) -------------
__device__ float g_T1[512 * 512];   // pos_emb @ W1[0:256,:]
__device__ float g_T3[512 * 512];   // pos_emb @ W1[512:768,:]
__device__ float g_TP[8 * 512];     // pred_emb @ W1[256:512,:] + b1
__device__ float g_TR[8 * 512];     // role_emb @ W1[512:768,:]
__device__ float g_agg[NNODE * 512];// per-node sum of gelu(h)
__device__ int   g_cnt[NNODE];      // zeroed by k_gemm epilogue each run
__device__ int   g_off[NNODE + 1];
__device__ int   g_fill[NNODE];
__device__ unsigned g_msgs[2 * NEDGE];
__device__ float g_pooled[BB * DD]; // zeroed by k_latent each run

// ------------- helpers -------------
__device__ __forceinline__ u64 ffma2(u64 a, u64 b, u64 c) {
    u64 d;
    asm("fma.rn.f32x2 %0, %1, %2, %3;" : "=l"(d) : "l"(a), "l"(b), "l"(c));
    return d;
}
__device__ __forceinline__ u64 dup2(float a) {
    u64 d;
    asm("mov.b64 %0, {%1, %1};" : "=l"(d) : "f"(a));
    return d;
}
__device__ __forceinline__ float2 unpk(u64 u) {
    float2 r;
    asm("mov.b64 {%0, %1}, %2;" : "=f"(r.x), "=f"(r.y) : "l"(u));
    return r;
}

// ------------- k1: precompute tables (FFMA2) + folded edge counting -------
// Tables: C[rows,512] = A[rows,256] @ W1[wOff:wOff+256, :]  (+ b1 for TP)
// grid (4, 16, 4): x = 128-col group, y = 32-row group, z = segment.
// Segments 2/3 only use y==0; their other 120 blocks run the edge count.
__global__ void __launch_bounds__(256) k_tables(const float* __restrict__ pos,
                                                const float* __restrict__ pre,
                                                const float* __restrict__ rol,
                                                const float* __restrict__ W1,
                                                const float* __restrict__ b1,
                                                const int* __restrict__ a0,
                                                const int* __restrict__ a1,
                                                const int* __restrict__ pr) {
    int seg = blockIdx.z;
    const float* A; float* C; int rowsTot; int wOff;
    if (seg == 0)      { A = pos; C = g_T1; rowsTot = 512; wOff = 0; }
    else if (seg == 1) { A = pos; C = g_T3; rowsTot = 512; wOff = 512; }
    else if (seg == 2) { A = pre; C = g_TP; rowsTot = 8;   wOff = 256; }
    else               { A = rol; C = g_TR; rowsTot = 8;   wOff = 512; }
    int r0 = blockIdx.y * 32;
    if (r0 >= rowsTot) {
        // ---- folded k_count on the 120 otherwise-idle blocks ----
        int cb = ((seg - 2) * 4 + blockIdx.x) * 15 + (blockIdx.y - 1);
        for (int e = cb * 256 + threadIdx.x; e < NEDGE; e += 120 * 256) {
            int b = e >> 11;
            int A0 = a0[e], A1 = a1[e], P = pr[e];
            int dst = (P == 1) ? A0 : A1;
            atomicAdd(&g_cnt[b * SS + dst], 1);
            if (P >= 2) atomicAdd(&g_cnt[b * SS + A0], 1);
        }
        return;
    }

    __shared__ float A_sm[32][256];
    int t = threadIdx.x;
    #pragma unroll
    for (int i = 0; i < 8; i++) {
        int fi = t + 256 * i;
        int row = fi >> 6, q = fi & 63;
        float4 v = make_float4(0.f, 0.f, 0.f, 0.f);
        if (r0 + row < rowsTot)
            v = *(const float4*)&A[(size_t)(r0 + row) * 256 + q * 4];
        A_sm[row][q * 4 + 0] = v.x; A_sm[row][q * 4 + 1] = v.y;
        A_sm[row][q * 4 + 2] = v.z; A_sm[row][q * 4 + 3] = v.w;
    }
    __syncthreads();

    int pi  = t & 63;
    int col = blockIdx.x * 128 + pi * 2;     // column pair
    int rg  = t >> 6;                        // 4 row groups of 8
    u64 acc[8];
    #pragma unroll
    for (int j = 0; j < 8; j++) acc[j] = 0ULL;

    #pragma unroll 2
    for (int k4 = 0; k4 < 64; k4++) {
        u64 w0 = *(const u64*)&W1[(size_t)(wOff + k4 * 4 + 0) * 512 + col];
        u64 w1 = *(const u64*)&W1[(size_t)(wOff + k4 * 4 + 1) * 512 + col];
        u64 w2 = *(const u64*)&W1[(size_t)(wOff + k4 * 4 + 2) * 512 + col];
        u64 w3 = *(const u64*)&W1[(size_t)(wOff + k4 * 4 + 3) * 512 + col];
        #pragma unroll
        for (int j = 0; j < 8; j++) {
            float4 a = *(const float4*)&A_sm[rg * 8 + j][k4 * 4];
            acc[j] = ffma2(dup2(a.x), w0, acc[j]);
            acc[j] = ffma2(dup2(a.y), w1, acc[j]);
            acc[j] = ffma2(dup2(a.z), w2, acc[j]);
            acc[j] = ffma2(dup2(a.w), w3, acc[j]);
        }
    }
    float2 bias = make_float2(0.f, 0.f);
    if (seg == 2) bias = *(const float2*)&b1[col];
    #pragma unroll
    for (int j = 0; j < 8; j++) {
        int r = r0 + rg * 8 + j;
        if (r < rowsTot) {
            float2 v = unpk(acc[j]);
            *(float2*)&C[(size_t)r * 512 + col] =
                make_float2(v.x + bias.x, v.y + bias.y);
        }
    }
}

// ------------- k2b: exclusive scan via warp shuffles (one block) -------------
__global__ void __launch_bounds__(1024) k_scan() {
    __shared__ int wsum[32];
    int t = threadIdx.x, lane = t & 31, warp = t >> 5;
    int base = t * 8;
    int loc[8], s = 0;
    #pragma unroll
    for (int i = 0; i < 8; i++) { loc[i] = g_cnt[base + i]; s += loc[i]; }
    int inc = s;
    #pragma unroll
    for (int o = 1; o < 32; o <<= 1) {
        int v = __shfl_up_sync(0xffffffffu, inc, o);
        if (lane >= o) inc += v;
    }
    if (lane == 31) wsum[warp] = inc;
    __syncthreads();
    if (warp == 0) {
        int ws = wsum[lane];
        int winc = ws;
        #pragma unroll
        for (int o = 1; o < 32; o <<= 1) {
            int v = __shfl_up_sync(0xffffffffu, winc, o);
            if (lane >= o) winc += v;
        }
        wsum[lane] = winc - ws;
    }
    __syncthreads();
    int excl = wsum[warp] + inc - s;
    #pragma unroll
    for (int i = 0; i < 8; i++) {
        g_off[base + i] = excl;
        g_fill[base + i] = excl;
        excl += loc[i];
    }
    if (t == 1023) g_off[NNODE] = excl;
}

// ------------- k2c: fill message descriptors -------------
// word: bits[0:9) T1 row, [9:18) third row, [18:21) pred, bit21 third-is-role
__global__ void k_fill(const int* __restrict__ a0, const int* __restrict__ a1,
                       const int* __restrict__ pr, const int* __restrict__ ro) {
    int e = blockIdx.x * 256 + threadIdx.x;
    if (e >= NEDGE) return;
    int b = e >> 11;
    int A0 = a0[e], A1 = a1[e], P = pr[e];
    int isr = (P == 1);
    int dstF = isr ? A0 : A1;
    int third = isr ? (ro[e] + 1) : A1;
    unsigned wf = (unsigned)A0 | ((unsigned)third << 9) | ((unsigned)P << 18) |
                  ((unsigned)isr << 21);
    int pos = atomicAdd(&g_fill[b * SS + dstF], 1);
    g_msgs[pos] = wf;
    if (P >= 2) {
        unsigned wb = (unsigned)A1 | ((unsigned)A0 << 9) | ((unsigned)P << 18);
        int pos2 = atomicAdd(&g_fill[b * SS + A0], 1);
        g_msgs[pos2] = wb;
    }
}

// ------------- k3: per-node gather + gelu accumulate (L2-resident tables) ----
__global__ void __launch_bounds__(128) k_gather() {
    int warp = (blockIdx.x * 128 + threadIdx.x) >> 5;
    int lane = threadIdx.x & 31;
    int n = warp;                       // node 0..8191 (grid = 2048 x 128)
    int beg = g_off[n], end = g_off[n + 1];
    float4 acc[4];
    #pragma unroll
    for (int i = 0; i < 4; i++) acc[i] = make_float4(0.f, 0.f, 0.f, 0.f);

    for (int m = beg; m < end; m++) {
        unsigned w = g_msgs[m];
        int r1 = w & 511;
        int r3 = (w >> 9) & 511;
        int p  = (w >> 18) & 7;
        const float* t3 = (w & (1u << 21)) ? g_TR : g_T3;
        const float* p1 = g_T1 + (size_t)r1 * 512;
        const float* pp = g_TP + (size_t)p * 512;
        const float* p3 = t3 + (size_t)r3 * 512;
        #pragma unroll
        for (int i = 0; i < 4; i++) {
            int k = i * 128 + lane * 4;
            float4 a = *(const float4*)(p1 + k);
            float4 b = *(const float4*)(pp + k);
            float4 c = *(const float4*)(p3 + k);
            // gelu(x) = 0.5x + x^2/sqrt(2pi) * (1 - x^2/6 + x^4/40); |x|<0.1
            {
                float x = a.x + b.x + c.x; float x2 = x * x;
                float q = fmaf(x2, 0.025f, -0.16666667f); q = fmaf(x2, q, 1.0f);
                acc[i].x = fmaf(0.5f, x, acc[i].x);
                acc[i].x = fmaf(0.3989422804f * x2, q, acc[i].x);
            }
            {
                float x = a.y + b.y + c.y; float x2 = x * x;
                float q = fmaf(x2, 0.025f, -0.16666667f); q = fmaf(x2, q, 1.0f);
                acc[i].y = fmaf(0.5f, x, acc[i].y);
                acc[i].y = fmaf(0.3989422804f * x2, q, acc[i].y);
            }
            {
                float x = a.z + b.z + c.z; float x2 = x * x;
                float q = fmaf(x2, 0.025f, -0.16666667f); q = fmaf(x2, q, 1.0f);
                acc[i].z = fmaf(0.5f, x, acc[i].z);
                acc[i].z = fmaf(0.3989422804f * x2, q, acc[i].z);
            }
            {
                float x = a.w + b.w + c.w; float x2 = x * x;
                float q = fmaf(x2, 0.025f, -0.16666667f); q = fmaf(x2, q, 1.0f);
                acc[i].w = fmaf(0.5f, x, acc[i].w);
                acc[i].w = fmaf(0.3989422804f * x2, q, acc[i].w);
            }
        }
    }
    float* g = g_agg + (size_t)n * 512;
    #pragma unroll
    for (int i = 0; i < 4; i++)
        *(float4*)(g + i * 128 + lane * 4) = acc[i];
}

// ------------- k4: node GEMM (8192x512 @ 512x256) + fused LN + pooled mean ----
// 512 threads, tile M=64, N=256. Warp w owns rows 4w..4w+3.
// Lane l owns col pairs {2l+64c}, c=0..3.
__global__ void __launch_bounds__(512) k_gemm(const float* __restrict__ W2,
                                              const float* __restrict__ pos,
                                              const float* __restrict__ b2,
                                              const float* __restrict__ lng,
                                              const float* __restrict__ lnb) {
    __shared__ __align__(16) float Gs[64][36];
    __shared__ __align__(16) float Ws[32][260];
    int t = threadIdx.x;
    int lane = t & 31, warp = t >> 5;
    int row0 = blockIdx.x * 64;

    u64 acc[4][4];
    #pragma unroll
    for (int j = 0; j < 4; j++)
        #pragma unroll
        for (int c = 0; c < 4; c++) acc[j][c] = 0ULL;

    for (int kc = 0; kc < 512; kc += 32) {
        {
            int q = t;                  // 512 float4s of G tile
            int r = q >> 3, c4 = q & 7;
            float4 v = *(const float4*)&g_agg[(size_t)(row0 + r) * 512 + kc + c4 * 4];
            Gs[r][c4 * 4 + 0] = v.x; Gs[r][c4 * 4 + 1] = v.y;
            Gs[r][c4 * 4 + 2] = v.z; Gs[r][c4 * 4 + 3] = v.w;
        }
        #pragma unroll
        for (int i = 0; i < 4; i++) {
            int q = t + i * 512;        // 2048 float4s of W2 chunk
            int r = q >> 6, c4 = q & 63;
            float4 v = *(const float4*)&W2[(size_t)(kc + r) * 256 + c4 * 4];
            Ws[r][c4 * 4 + 0] = v.x; Ws[r][c4 * 4 + 1] = v.y;
            Ws[r][c4 * 4 + 2] = v.z; Ws[r][c4 * 4 + 3] = v.w;
        }
        __syncthreads();
        #pragma unroll 4
        for (int kk = 0; kk < 32; kk++) {
            u64 bp[4];
            #pragma unroll
            for (int c = 0; c < 4; c++)
                bp[c] = *(const u64*)&Ws[kk][2 * lane + 64 * c];
            #pragma unroll
            for (int j = 0; j < 4; j++) {
                u64 av = dup2(Gs[4 * warp + j][kk]);
                #pragma unroll
                for (int c = 0; c < 4; c++) acc[j][c] = ffma2(av, bp[c], acc[j][c]);
            }
        }
        __syncthreads();
    }

    // epilogue: x = C + pos_emb[s] + cnt*b2 ; LayerNorm ; pooled sum
    float2 glv[4], blv[4], b2v[4];
    #pragma unroll
    for (int c = 0; c < 4; c++) {
        glv[c] = *(const float2*)&lng[2 * lane + 64 * c];
        blv[c] = *(const float2*)&lnb[2 * lane + 64 * c];
        b2v[c] = *(const float2*)&b2[2 * lane + 64 * c];
    }
    float2 pool[4];
    #pragma unroll
    for (int c = 0; c < 4; c++) pool[c] = make_float2(0.f, 0.f);

    int rbase = row0 + 4 * warp;
    #pragma unroll
    for (int j = 0; j < 4; j++) {
        int rg = rbase + j;
        int s = rg & 511;
        float cr = (float)g_cnt[rg];
        if (lane == 0) g_cnt[rg] = 0;      // re-zero for next run
        float2 xv[4];
        float s1 = 0.f, s2 = 0.f;
        #pragma unroll
        for (int c = 0; c < 4; c++) {
            float2 pe = *(const float2*)&pos[(size_t)s * 256 + 2 * lane + 64 * c];
            float2 a = unpk(acc[j][c]);
            float x0 = a.x + pe.x + cr * b2v[c].x;
            float x1 = a.y + pe.y + cr * b2v[c].y;
            xv[c] = make_float2(x0, x1);
            s1 += x0 + x1;
            s2 = fmaf(x0, x0, s2);
            s2 = fmaf(x1, x1, s2);
        }
        #pragma unroll
        for (int off = 16; off > 0; off >>= 1) {
            s1 += __shfl_xor_sync(0xffffffff, s1, off);
            s2 += __shfl_xor_sync(0xffffffff, s2, off);
        }
        float mu = s1 * (1.0f / 256.0f);
        float var = fmaf(-mu, mu, s2 * (1.0f / 256.0f));
        float iv = rsqrtf(var + 1e-5f);
        #pragma unroll
        for (int c = 0; c < 4; c++) {
            float n0 = fmaf((xv[c].x - mu) * iv, glv[c].x, blv[c].x);
            float n1 = fmaf((xv[c].y - mu) * iv, glv[c].y, blv[c].y);
            pool[c].x += n0;
            pool[c].y += n1;
        }
    }
    int bb = rbase >> 9;
    float* pp = g_pooled + bb * 256;
    #pragma unroll
    for (int c = 0; c < 4; c++) {
        atomicAdd(&pp[2 * lane + 64 * c + 0], pool[c].x * (1.0f / 512.0f));
        atomicAdd(&pp[2 * lane + 64 * c + 1], pool[c].y * (1.0f / 512.0f));
    }
}

// ------------- k5: latent MLP (16x256 -> 16x512) -------------
__global__ void __launch_bounds__(512) k_latent(const float* __restrict__ Wl1,
                                                const float* __restrict__ bl1,
                                                const float* __restrict__ Wl2,
                                                const float* __restrict__ bl2,
                                                float* __restrict__ out) {
    __shared__ float ps[256];
    __shared__ float mid[512];
    int b = blockIdx.x, t = threadIdx.x;
    if (t < 256) {
        ps[t] = g_pooled[b * 256 + t];
        g_pooled[b * 256 + t] = 0.0f;      // re-zero for next run
    }
    __syncthreads();
    float a0 = 0.f, a1 = 0.f, a2 = 0.f, a3 = 0.f;
    #pragma unroll 4
    for (int k = 0; k < 256; k += 4) {
        a0 = fmaf(ps[k + 0], Wl1[(size_t)(k + 0) * 512 + t], a0);
        a1 = fmaf(ps[k + 1], Wl1[(size_t)(k + 1) * 512 + t], a1);
        a2 = fmaf(ps[k + 2], Wl1[(size_t)(k + 2) * 512 + t], a2);
        a3 = fmaf(ps[k + 3], Wl1[(size_t)(k + 3) * 512 + t], a3);
    }
    float h = a0 + a1 + a2 + a3 + bl1[t];
    mid[t] = 0.5f * h * (1.0f + erff(h * 0.7071067811865476f));
    __syncthreads();
    a0 = a1 = a2 = a3 = 0.f;
    #pragma unroll 4
    for (int j = 0; j < 512; j += 4) {
        a0 = fmaf(mid[j + 0], Wl2[(size_t)(j + 0) * 512 + t], a0);
        a1 = fmaf(mid[j + 1], Wl2[(size_t)(j + 1) * 512 + t], a1);
        a2 = fmaf(mid[j + 2], Wl2[(size_t)(j + 2) * 512 + t], a2);
        a3 = fmaf(mid[j + 3], Wl2[(size_t)(j + 3) * 512 + t], a3);
    }
    out[b * 512 + t] = a0 + a1 + a2 + a3 + bl2[t];
}

// ------------- launch -------------
extern "C" void kernel_launch(void* const* d_in, const int* in_sizes, int n_in,
                              void* d_out, int out_size) {
    const int* a0 = (const int*)d_in[0];
    const int* a1 = (const int*)d_in[1];
    const int* pr = (const int*)d_in[2];
    const int* ro = (const int*)d_in[3];
    int base = (n_in > 4 && in_sizes[4] == 1) ? 5 : 4;
    const float* pos = (const float*)d_in[base + 0];
    const float* pre = (const float*)d_in[base + 1];
    const float* rol = (const float*)d_in[base + 2];
    const float* W1  = (const float*)d_in[base + 3];
    const float* b1  = (const float*)d_in[base + 4];
    const float* W2  = (const float*)d_in[base + 5];
    const float* b2  = (const float*)d_in[base + 6];
    const float* lng = (const float*)d_in[base + 7];
    const float* lnb = (const float*)d_in[base + 8];
    const float* Wl1 = (const float*)d_in[base + 9];
    const float* bl1 = (const float*)d_in[base + 10];
    const float* Wl2 = (const float*)d_in[base + 11];
    const float* bl2 = (const float*)d_in[base + 12];
    float* out = (float*)d_out;

    k_tables<<<dim3(4, 16, 4), 256>>>(pos, pre, rol, W1, b1, a0, a1, pr);
    k_scan<<<1, 1024>>>();
    k_fill<<<NEDGE / 256, 256>>>(a0, a1, pr, ro);
    k_gather<<<NNODE / 4, 128>>>();
    k_gemm<<<NNODE / 64, 512>>>(W2, pos, b2, lng, lnb);
    k_latent<<<BB, 512>>>(Wl1, bl1, Wl2, bl2, out);
}